// round 8
// baseline (speedup 1.0000x reference)
#include <cuda_runtime.h>
#include <cstdint>

// ---------------- problem constants ----------------
constexpr int B    = 32768;
constexpr int FG   = 4;            // feature groups (split across CTAs, atomicAdd combine)
constexpr int FPG  = 50;           // features per group
constexpr int FC   = 5;            // features per smem chunk
constexpr int NCH  = FPG / FC;     // 10

constexpr int TPB      = 128;      // 4 warps; warp owns 64 rows
constexpr int ROWS_CTA = 256;
constexpr int NRB      = B / ROWS_CTA;   // 128 row blocks
constexpr int GRID     = FG * NRB;       // 512

// ---------------- smem layout (float offsets) ----------------
constexpr int YPITCH = 27;                         // 25 used + pad
constexpr int OFF_Y  = 0;                          // [256][27] tf32 y
constexpr int OFF_W1 = OFF_Y + ROWS_CTA * YPITCH;  // 6912  [FC][8k][17] (k5=b1, k6,7=0; h15=0)
constexpr int OFF_W2 = OFF_W1 + FC * 8 * 17;       // 7592  [FC][16k][33] (k15=b2; n30,31=0)
constexpr int OFF_W3 = OFF_W2 + FC * 16 * 33;      // 10232 [FC][32] fp32 (n30,31=0)
constexpr int OFF_H1 = OFF_W3 + FC * 32;           // 10392 [4 warps][64][17] tf32 h1 (col15=1.0)
constexpr int SMEM_FLOATS = OFF_H1 + 4 * 64 * 17;  // 14744
constexpr int SMEM_BYTES  = SMEM_FLOATS * 4;       // 58976

// ---------------- helpers ----------------
__device__ __forceinline__ uint32_t f2tf(float x) {   // fp32 -> tf32 bits (round-to-nearest)
    uint32_t r; asm("cvt.rna.tf32.f32 %0, %1;" : "=r"(r) : "f"(x)); return r;
}
__device__ __forceinline__ void mma8(float& d0, float& d1, float& d2, float& d3,
                                     uint32_t a0, uint32_t a1, uint32_t a2, uint32_t a3,
                                     uint32_t b0, uint32_t b1,
                                     float c0, float c1, float c2, float c3) {
    asm volatile(
        "mma.sync.aligned.m16n8k8.row.col.f32.tf32.tf32.f32 "
        "{%0,%1,%2,%3}, {%4,%5,%6,%7}, {%8,%9}, {%10,%11,%12,%13};"
        : "=f"(d0), "=f"(d1), "=f"(d2), "=f"(d3)
        : "r"(a0), "r"(a1), "r"(a2), "r"(a3), "r"(b0), "r"(b1),
          "f"(c0), "f"(c1), "f"(c2), "f"(c3));
}

__global__ void init_out_kernel(const float* __restrict__ b3, float* __restrict__ out) {
    int i = blockIdx.x * blockDim.x + threadIdx.x;
    out[i] = __ldg(b3);
}

__global__ __launch_bounds__(TPB, 2)
void mlp_mma_kernel(const float* __restrict__ y,
                    const float* __restrict__ W1,
                    const float* __restrict__ b1,
                    const float* __restrict__ W2,
                    const float* __restrict__ b2,
                    const float* __restrict__ W3,
                    float* __restrict__ out)
{
    extern __shared__ float smem[];
    const int tid = threadIdx.x;
    const int bq  = blockIdx.x >> 7;     // feature group 0..3
    const int br  = blockIdx.x & 127;    // row block
    const int rowbase = br * ROWS_CTA;

    const int lane = tid & 31;
    const int wid  = tid >> 5;
    const int g    = lane >> 2;          // groupID (row within tile)
    const int t    = lane & 3;           // threadID in group (k / col pair)
    const int wrow = wid * 64;           // warp's row base within CTA

    float* h1w = &smem[OFF_H1 + wid * (64 * 17)];
    const uint32_t one_tf = __float_as_uint(1.0f);

    float acc[4][2];
    #pragma unroll
    for (int m = 0; m < 4; ++m) { acc[m][0] = 0.f; acc[m][1] = 0.f; }

    for (int c = 0; c < NCH; ++c) {
        const int f0 = bq * FPG + c * FC;
        __syncthreads();

        // ---- stage y (tf32), coalesced ----
        for (int i = tid; i < ROWS_CTA * 25; i += TPB) {
            int r = i / 25, j = i % 25;
            smem[OFF_Y + r * YPITCH + j] =
                __uint_as_float(f2tf(__ldg(y + (size_t)(rowbase + r) * 1000 + f0 * 5 + j)));
        }
        // ---- stage W1aug [fl][k=0..7][h=0..15]: k<5 = W1, k==5 = b1, else 0; h15 = 0 ----
        for (int i = tid; i < FC * 128; i += TPB) {
            int fl = i >> 7, r = i & 127, k = r >> 4, h = r & 15;
            float v = 0.f;
            if (h < 15) {
                if (k < 5)       v = __ldg(W1 + (f0 + fl) * 75 + k * 15 + h);
                else if (k == 5) v = __ldg(b1 + (f0 + fl) * 15 + h);
            }
            smem[OFF_W1 + fl * 136 + k * 17 + h] = __uint_as_float(f2tf(v));
        }
        // ---- stage W2T [fl][k=0..15][n=0..31]: k<15 = W2[h=k][o=n], k==15 = b2; n>=30 -> 0 ----
        for (int i = tid; i < FC * 512; i += TPB) {
            int fl = i >> 9, r = i & 511, k = r >> 5, n = r & 31;
            float v = 0.f;
            if (n < 30)
                v = (k < 15) ? __ldg(W2 + (f0 + fl) * 450 + k * 30 + n)
                             : __ldg(b2 + (f0 + fl) * 30 + n);
            smem[OFF_W2 + fl * 528 + k * 33 + n] = __uint_as_float(f2tf(v));
        }
        // ---- stage w3 (fp32) ----
        for (int i = tid; i < FC * 32; i += TPB) {
            int fl = i >> 5, n = i & 31;
            smem[OFF_W3 + fl * 32 + n] = (n < 30) ? __ldg(W3 + (f0 + fl) * 30 + n) : 0.f;
        }
        __syncthreads();

        #pragma unroll 1
        for (int fl = 0; fl < FC; ++fl) {
            const float* ysf = &smem[OFF_Y];
            const float* w1f = &smem[OFF_W1 + fl * 136];
            const float* w2f = &smem[OFF_W2 + fl * 528];
            const float* w3f = &smem[OFF_W3 + fl * 32];
            const int ycol = fl * 5;

            // ======== layer 1: [64 x 8aug] @ [8 x 16] per warp ========
            uint32_t w1b[2][2];
            #pragma unroll
            for (int nt = 0; nt < 2; ++nt) {
                w1b[nt][0] = __float_as_uint(w1f[t * 17 + nt * 8 + g]);        // B[k=t][n]
                w1b[nt][1] = __float_as_uint(w1f[(t + 4) * 17 + nt * 8 + g]);  // B[k=t+4][n]
            }
            #pragma unroll
            for (int m = 0; m < 4; ++m) {
                int r0 = wrow + m * 16 + g;
                uint32_t a0 = __float_as_uint(ysf[r0 * YPITCH + ycol + t]);
                uint32_t a1 = __float_as_uint(ysf[(r0 + 8) * YPITCH + ycol + t]);
                uint32_t a2, a3;
                if (t == 0) {                                  // col 4 = y[4]
                    a2 = __float_as_uint(ysf[r0 * YPITCH + ycol + 4]);
                    a3 = __float_as_uint(ysf[(r0 + 8) * YPITCH + ycol + 4]);
                } else if (t == 1) { a2 = one_tf; a3 = one_tf; }  // aug col 5 = 1
                else               { a2 = 0u;     a3 = 0u;     }  // cols 6,7 = 0

                float d00, d01, d02, d03, d10, d11, d12, d13;
                mma8(d00, d01, d02, d03, a0, a1, a2, a3, w1b[0][0], w1b[0][1], 0.f, 0.f, 0.f, 0.f);
                mma8(d10, d11, d12, d13, a0, a1, a2, a3, w1b[1][0], w1b[1][1], 0.f, 0.f, 0.f, 0.f);

                int rr = m * 16 + g;
                h1w[rr * 17 + 2 * t]           = __uint_as_float(f2tf(d00));
                h1w[rr * 17 + 2 * t + 1]       = __uint_as_float(f2tf(d01));
                h1w[(rr + 8) * 17 + 2 * t]     = __uint_as_float(f2tf(d02));
                h1w[(rr + 8) * 17 + 2 * t + 1] = __uint_as_float(f2tf(d03));
                h1w[rr * 17 + 8 + 2 * t]       = __uint_as_float(f2tf(d10));
                h1w[rr * 17 + 8 + 2 * t + 1]   = (t == 3) ? 1.0f : __uint_as_float(f2tf(d11));
                h1w[(rr + 8) * 17 + 8 + 2 * t]     = __uint_as_float(f2tf(d12));
                h1w[(rr + 8) * 17 + 8 + 2 * t + 1] = (t == 3) ? 1.0f : __uint_as_float(f2tf(d13));
            }
            __syncwarp();

            // ======== layer 2: [64 x 16] @ [16 x 32] per warp ========
            uint32_t A2[4][2][4];
            #pragma unroll
            for (int m = 0; m < 4; ++m) {
                int rr = m * 16 + g;
                #pragma unroll
                for (int s = 0; s < 2; ++s) {
                    A2[m][s][0] = __float_as_uint(h1w[rr * 17 + 8 * s + t]);
                    A2[m][s][1] = __float_as_uint(h1w[(rr + 8) * 17 + 8 * s + t]);
                    A2[m][s][2] = __float_as_uint(h1w[rr * 17 + 8 * s + t + 4]);
                    A2[m][s][3] = __float_as_uint(h1w[(rr + 8) * 17 + 8 * s + t + 4]);
                }
            }
            #pragma unroll
            for (int nt = 0; nt < 4; ++nt) {
                uint32_t b0a = __float_as_uint(w2f[t * 33 + nt * 8 + g]);
                uint32_t b1a = __float_as_uint(w2f[(t + 4) * 33 + nt * 8 + g]);
                uint32_t b0b = __float_as_uint(w2f[(t + 8) * 33 + nt * 8 + g]);
                uint32_t b1b = __float_as_uint(w2f[(t + 12) * 33 + nt * 8 + g]);
                float2 w3v = *reinterpret_cast<const float2*>(&w3f[nt * 8 + 2 * t]);
                #pragma unroll
                for (int m = 0; m < 4; ++m) {
                    float d0, d1, d2, d3;
                    mma8(d0, d1, d2, d3,
                         A2[m][0][0], A2[m][0][1], A2[m][0][2], A2[m][0][3],
                         b0a, b1a, 0.f, 0.f, 0.f, 0.f);
                    mma8(d0, d1, d2, d3,
                         A2[m][1][0], A2[m][1][1], A2[m][1][2], A2[m][1][3],
                         b0b, b1b, d0, d1, d2, d3);
                    acc[m][0] = fmaf(fmaxf(d0, 0.f), w3v.x, fmaf(fmaxf(d1, 0.f), w3v.y, acc[m][0]));
                    acc[m][1] = fmaf(fmaxf(d2, 0.f), w3v.x, fmaf(fmaxf(d3, 0.f), w3v.y, acc[m][1]));
                }
            }
            __syncwarp();   // layer-2 LDS done before next feature overwrites h1w
        }
    }

    // quad-reduce per-row sums and combine feature groups
    #pragma unroll
    for (int m = 0; m < 4; ++m) {
        #pragma unroll
        for (int i = 0; i < 2; ++i) {
            float v = acc[m][i];
            v += __shfl_xor_sync(0xffffffffu, v, 1);
            v += __shfl_xor_sync(0xffffffffu, v, 2);
            if (t == 0)
                atomicAdd(out + rowbase + wrow + m * 16 + i * 8 + g, v);
        }
    }
}

extern "C" void kernel_launch(void* const* d_in, const int* in_sizes, int n_in,
                              void* d_out, int out_size)
{
    const float* y  = (const float*)d_in[0];
    const float* W1 = (const float*)d_in[1];
    const float* b1 = (const float*)d_in[2];
    const float* W2 = (const float*)d_in[3];
    const float* b2 = (const float*)d_in[4];
    const float* W3 = (const float*)d_in[5];
    const float* b3 = (const float*)d_in[6];
    float* out = (float*)d_out;

    cudaFuncSetAttribute(mlp_mma_kernel, cudaFuncAttributeMaxDynamicSharedMemorySize, SMEM_BYTES);

    init_out_kernel<<<B / 256, 256>>>(b3, out);
    mlp_mma_kernel<<<GRID, TPB, SMEM_BYTES>>>(y, W1, b1, W2, b2, W3, out);
}

// round 9
// speedup vs baseline: 1.8309x; 1.8309x over previous
#include <cuda_runtime.h>
#include <cstdint>

// ---------------- problem constants ----------------
constexpr int B    = 32768;
constexpr int S    = 8;             // feature eighths
constexpr int FPG  = 25;            // features per group
constexpr int FC   = 5;             // features per smem chunk
constexpr int NCH  = FPG / FC;      // 5

constexpr int TPB  = 128;
constexpr int RB   = 128;           // row blocks
constexpr int GRID = S * RB;        // 1024
constexpr int HALF = RB * TPB;      // 16384 (R=2: rowB = rowA + HALF; 2*16384 = B exactly)

constexpr int YPITCH = 27;          // 25 data + pad (odd -> conflict-free)

// ---------------- smem layout (float offsets; vector-read regions 16B-aligned) ----------------
constexpr int OFF_YA = 0;                        // [128][27]
constexpr int OFF_YB = OFF_YA + TPB * YPITCH;    // 3456
constexpr int OFF_W1 = OFF_YB + TPB * YPITCH;    // 6912  [f][d][16]
constexpr int OFF_B1 = OFF_W1 + FC * 80;         // 7312  [f][16]
constexpr int OFF_W2 = OFF_B1 + FC * 16;         // 7392  [f][h][32]
constexpr int OFF_B2 = OFF_W2 + FC * 480;        // 9792  [f][32]
constexpr int OFF_W3 = OFF_B2 + FC * 32;         // 9952  [f][32]
constexpr int SMEM_FLOATS = OFF_W3 + FC * 32;    // 10112 -> 40448 B static (x5 CTAs = 202KB)

typedef unsigned long long u64;

__device__ __forceinline__ u64 pack2(float lo, float hi) {
    u64 r; asm("mov.b64 %0, {%1, %2};" : "=l"(r) : "f"(lo), "f"(hi)); return r;
}
__device__ __forceinline__ void unpack2(u64 v, float& lo, float& hi) {
    asm("mov.b64 {%0, %1}, %2;" : "=f"(lo), "=f"(hi) : "l"(v));
}
__device__ __forceinline__ void fma2(u64& d, u64 a, u64 b) {
    asm("fma.rn.f32x2 %0, %1, %2, %0;" : "+l"(d) : "l"(a), "l"(b));
}

__global__ void init_out_kernel(const float* __restrict__ b3, float* __restrict__ out) {
    int i = blockIdx.x * blockDim.x + threadIdx.x;
    out[i] = __ldg(b3);
}

// Layer-2 pass over outputs [P0, P0 + 2*NU): NU u64 accumulators per row.
template<int P0, int NU>
__device__ __forceinline__ void l2pass(const float* __restrict__ smem, int fl,
                                       const float* __restrict__ hA, const float* __restrict__ hB,
                                       float& accA0, float& accA1, float& accB0, float& accB1)
{
    u64 sA[NU], sB[NU];
    {
        const float* bsrc = &smem[OFF_B2 + fl * 32 + P0];
        #pragma unroll
        for (int i = 0; i < NU / 2; ++i) {
            ulonglong2 v = reinterpret_cast<const ulonglong2*>(bsrc)[i];
            sA[2*i] = v.x; sA[2*i+1] = v.y;
            sB[2*i] = v.x; sB[2*i+1] = v.y;
        }
        if (NU & 1) {
            u64 v = reinterpret_cast<const u64*>(bsrc)[NU - 1];
            sA[NU-1] = v; sB[NU-1] = v;
        }
    }
    #pragma unroll
    for (int h = 0; h < 15; ++h) {
        u64 hhA = pack2(hA[h], hA[h]);
        u64 hhB = pack2(hB[h], hB[h]);
        const float* wsrc = &smem[OFF_W2 + fl * 480 + h * 32 + P0];
        #pragma unroll
        for (int i = 0; i < NU / 2; ++i) {
            ulonglong2 v = reinterpret_cast<const ulonglong2*>(wsrc)[i];
            fma2(sA[2*i],   v.x, hhA);
            fma2(sA[2*i+1], v.y, hhA);
            fma2(sB[2*i],   v.x, hhB);
            fma2(sB[2*i+1], v.y, hhB);
        }
        if (NU & 1) {
            u64 v = reinterpret_cast<const u64*>(wsrc)[NU - 1];
            fma2(sA[NU-1], v, hhA);
            fma2(sB[NU-1], v, hhB);
        }
    }
    const float2* w3p = reinterpret_cast<const float2*>(&smem[OFF_W3 + fl * 32 + P0]);
    #pragma unroll
    for (int i = 0; i < NU; ++i) {
        float2 w = w3p[i];
        float x0, x1, z0, z1;
        unpack2(sA[i], x0, x1);
        unpack2(sB[i], z0, z1);
        accA0 = fmaf(fmaxf(x0, 0.f), w.x, accA0);
        accA1 = fmaf(fmaxf(x1, 0.f), w.y, accA1);
        accB0 = fmaf(fmaxf(z0, 0.f), w.x, accB0);
        accB1 = fmaf(fmaxf(z1, 0.f), w.y, accB1);
    }
}

__global__ __launch_bounds__(TPB, 5)
void mlp_fused_kernel(const float* __restrict__ y,
                      const float* __restrict__ W1,
                      const float* __restrict__ b1,
                      const float* __restrict__ W2,
                      const float* __restrict__ b2,
                      const float* __restrict__ W3,
                      float* __restrict__ out)
{
    __shared__ float smem[SMEM_FLOATS];

    const int tid = threadIdx.x;
    const int bq  = blockIdx.x >> 7;        // feature group 0..7
    const int br  = blockIdx.x & 127;       // row block 0..127

    const int rowA = br * TPB + tid;        // < 16384
    const int rowB = rowA + HALF;           // < 32768 (exact cover, no clamp)

    float accA0 = 0.f, accA1 = 0.f, accB0 = 0.f, accB1 = 0.f;

    for (int c = 0; c < NCH; ++c) {
        const int f0 = bq * FPG + c * FC;

        __syncthreads();

        // ---- stage y tiles (coalesced 100B row segments), both row sets ----
        for (int i = tid; i < TPB * 25; i += TPB) {
            int r = i / 25, cc = i % 25;
            smem[OFF_YA + r * YPITCH + cc] = __ldg(y + (size_t)(br * TPB + r) * 1000 + f0 * 5 + cc);
            smem[OFF_YB + r * YPITCH + cc] = __ldg(y + (size_t)(br * TPB + r + HALF) * 1000 + f0 * 5 + cc);
        }
        // ---- stage weights (padded layouts) ----
        for (int i = tid; i < FC * 75; i += TPB) {
            int f = i / 75, r = i % 75, d = r / 15, h = r % 15;
            smem[OFF_W1 + f * 80 + d * 16 + h] = W1[f0 * 75 + i];
        }
        for (int i = tid; i < FC * 15; i += TPB) {
            int f = i / 15, h = i % 15;
            smem[OFF_B1 + f * 16 + h] = b1[f0 * 15 + i];
        }
        for (int i = tid; i < FC * 450; i += TPB) {
            int f = i / 450, r = i % 450, h = r / 30, o = r % 30;
            smem[OFF_W2 + f * 480 + h * 32 + o] = W2[f0 * 450 + i];
        }
        for (int i = tid; i < FC * 30; i += TPB) {
            int f = i / 30, o = i % 30;
            smem[OFF_B2 + f * 32 + o] = b2[f0 * 30 + i];
            smem[OFF_W3 + f * 32 + o] = W3[f0 * 30 + i];
        }
        __syncthreads();

        #pragma unroll 1
        for (int fl = 0; fl < FC; ++fl) {
            // ---- y from smem (pitch 27 -> conflict-free) ----
            const float* yAp = &smem[OFF_YA + tid * YPITCH + fl * 5];
            const float* yBp = &smem[OFF_YB + tid * YPITCH + fl * 5];
            u64 ydA[5], ydB[5];
            #pragma unroll
            for (int d = 0; d < 5; ++d) {
                float va = yAp[d], vb = yBp[d];
                ydA[d] = pack2(va, va);
                ydB[d] = pack2(vb, vb);
            }

            // ---- layer 1 (packed): 8 pairs; pair-7 hi = padding, never consumed ----
            u64 h1A[8], h1B[8];
            {
                const ulonglong2* bv = reinterpret_cast<const ulonglong2*>(&smem[OFF_B1 + fl * 16]);
                #pragma unroll
                for (int j = 0; j < 4; ++j) {
                    ulonglong2 v = bv[j];
                    h1A[2*j] = v.x; h1A[2*j+1] = v.y;
                    h1B[2*j] = v.x; h1B[2*j+1] = v.y;
                }
            }
            #pragma unroll
            for (int d = 0; d < 5; ++d) {
                const ulonglong2* wv = reinterpret_cast<const ulonglong2*>(&smem[OFF_W1 + fl * 80 + d * 16]);
                #pragma unroll
                for (int j = 0; j < 4; ++j) {
                    ulonglong2 v = wv[j];
                    fma2(h1A[2*j],   v.x, ydA[d]);
                    fma2(h1A[2*j+1], v.y, ydA[d]);
                    fma2(h1B[2*j],   v.x, ydB[d]);
                    fma2(h1B[2*j+1], v.y, ydB[d]);
                }
            }

            float hA[16], hB[16];
            #pragma unroll
            for (int j = 0; j < 8; ++j) {
                unpack2(h1A[j], hA[2*j], hA[2*j+1]);
                unpack2(h1B[j], hB[2*j], hB[2*j+1]);
            }

            // ---- layer 2 in three register-light passes: outputs [0,12), [12,24), [24,30) ----
            l2pass< 0, 6>(smem, fl, hA, hB, accA0, accA1, accB0, accB1);
            l2pass<12, 6>(smem, fl, hA, hB, accA0, accA1, accB0, accB1);
            l2pass<24, 3>(smem, fl, hA, hB, accA0, accA1, accB0, accB1);
        }
    }

    // combine feature-group partials; out pre-initialized to b3
    atomicAdd(out + rowA, accA0 + accA1);
    atomicAdd(out + rowB, accB0 + accB1);
}

extern "C" void kernel_launch(void* const* d_in, const int* in_sizes, int n_in,
                              void* d_out, int out_size)
{
    const float* y  = (const float*)d_in[0];
    const float* W1 = (const float*)d_in[1];
    const float* b1 = (const float*)d_in[2];
    const float* W2 = (const float*)d_in[3];
    const float* b2 = (const float*)d_in[4];
    const float* W3 = (const float*)d_in[5];
    const float* b3 = (const float*)d_in[6];
    float* out = (float*)d_out;

    init_out_kernel<<<B / 256, 256>>>(b3, out);
    mlp_fused_kernel<<<GRID, TPB>>>(y, W1, b1, W2, b2, W3, out);
}